// round 11
// baseline (speedup 1.0000x reference)
#include <cuda_runtime.h>
#include <cstdint>

// out[b,o] = sum_i w_out[o,i] * sin(x[b,i]*w_sin[o,i] + b_sin[o,i]) + b_out[o]
// B=2048, I=256, O=512.
// v6: NO smem, NO barriers. One-time repack to i-major layouts:
//   pk[i][o] = (w_out, w_sin, b_sin, pad)  -> one coalesced LDG.128 per i-step
//   xT[i][b]                               -> two broadcast LDG.128 per i-step
// Inner loop: p=2 poly sins (FFMA-imm) + 6 MUFU sins per 8-b group.

#define B_DIM 2048
#define I_DIM 256
#define O_DIM 512

#define BM 32   // b-tile per block
#define BO 32   // o-tile per block

// ---------------- scratch (device globals: allocation-free rule) ----------------
__device__ float4 g_pk[I_DIM * O_DIM];   // 2 MB  (w_out, w_sin, b_sin, 0)
__device__ float  g_xT[I_DIM * B_DIM];   // 2 MB  xT[i][b]

// degree-15 odd Taylor sin; literal coefficients -> FFMA-imm
__device__ __forceinline__ float poly_sin(float u) {
    float s = u * u;
    float p = -7.6471637e-13f;                 // -1/15!
    p = fmaf(p, s,  1.6059044e-10f);           // +1/13!
    p = fmaf(p, s, -2.5052108e-08f);           // -1/11!
    p = fmaf(p, s,  2.7557319e-06f);           // +1/9!
    p = fmaf(p, s, -1.9841270e-04f);           // -1/7!
    p = fmaf(p, s,  8.3333333e-03f);           // +1/5!
    p = fmaf(p, s, -1.6666667e-01f);           // -1/3!
    p = fmaf(p, s,  1.0f);
    return u * p;
}

// ---------------- prep: pack (w_out, w_sin, b_sin) i-major ----------------
__global__ __launch_bounds__(256)
void pack_w_kernel(const float* __restrict__ weight, const float* __restrict__ bias) {
    int idx = blockIdx.x * 256 + threadIdx.x;   // i*O + o  (coalesced write)
    int o = idx & (O_DIM - 1);
    int i = idx >> 9;
    float2 w = ((const float2*)weight)[(size_t)o * I_DIM + i];
    float  b = bias[(size_t)o * (I_DIM + 1) + i];
    g_pk[idx] = make_float4(w.x, w.y, b, 0.0f);
}

// ---------------- prep: transpose x to i-major ----------------
__global__ __launch_bounds__(256)
void pack_x_kernel(const float* __restrict__ x) {
    int idx = blockIdx.x * 256 + threadIdx.x;   // i*B + b  (coalesced write)
    int b = idx & (B_DIM - 1);
    int i = idx >> 11;
    g_xT[idx] = x[(size_t)b * I_DIM + i];
}

// ---------------- main: streaming, no smem ----------------
__global__ __launch_bounds__(128, 8)
void trigo_linear_kernel(const float* __restrict__ bias,
                         float* __restrict__ out)
{
    const int tid     = threadIdx.x;       // 128 threads = 4 warps
    const int o_local = tid & 31;
    const int bg      = tid >> 5;          // warp -> b-group (8 b's)
    const int b_tile  = blockIdx.x * BM;
    const int o       = blockIdx.y * BO + o_local;
    const int bg8     = bg * 8;

    const float4* __restrict__ pk = g_pk + o;                    // + i*O_DIM
    const float*  __restrict__ xr = g_xT + b_tile + bg8;         // + i*B_DIM

    float acc[8];
    #pragma unroll
    for (int k = 0; k < 8; k++) acc[k] = 0.0f;

    #pragma unroll 8
    for (int i = 0; i < I_DIM; i++) {
        float4 P  = __ldg(&pk[(size_t)i * O_DIM]);        // lane-coalesced LDG.128
        float4 xa = *(const float4*)&xr[(size_t)i * B_DIM];      // broadcast
        float4 xb = *(const float4*)&xr[(size_t)i * B_DIM + 4];  // broadcast

        acc[0] = fmaf(P.x, poly_sin(fmaf(xa.x, P.y, P.z)), acc[0]);
        acc[1] = fmaf(P.x, poly_sin(fmaf(xa.y, P.y, P.z)), acc[1]);
        acc[2] = fmaf(P.x, __sinf(fmaf(xa.z, P.y, P.z)), acc[2]);
        acc[3] = fmaf(P.x, __sinf(fmaf(xa.w, P.y, P.z)), acc[3]);
        acc[4] = fmaf(P.x, __sinf(fmaf(xb.x, P.y, P.z)), acc[4]);
        acc[5] = fmaf(P.x, __sinf(fmaf(xb.y, P.y, P.z)), acc[5]);
        acc[6] = fmaf(P.x, __sinf(fmaf(xb.z, P.y, P.z)), acc[6]);
        acc[7] = fmaf(P.x, __sinf(fmaf(xb.w, P.y, P.z)), acc[7]);
    }

    const float b_out = bias[(size_t)o * (I_DIM + 1) + I_DIM];

    // warp lanes write consecutive o -> coalesced 128B rows
    #pragma unroll
    for (int k = 0; k < 8; k++) {
        out[(size_t)(b_tile + bg8 + k) * O_DIM + o] = acc[k] + b_out;
    }
}

extern "C" void kernel_launch(void* const* d_in, const int* in_sizes, int n_in,
                              void* d_out, int out_size)
{
    const float* x      = (const float*)d_in[0];
    const float* weight = (const float*)d_in[1];
    const float* bias   = (const float*)d_in[2];
    float* out          = (float*)d_out;

    pack_w_kernel<<<(I_DIM * O_DIM) / 256, 256>>>(weight, bias);
    pack_x_kernel<<<(I_DIM * B_DIM) / 256, 256>>>(x);

    dim3 grid(B_DIM / BM, O_DIM / BO);   // 64 x 16 = 1024 blocks, 128 thr each
    trigo_linear_kernel<<<grid, 128>>>(bias, out);
}

// round 13
// speedup vs baseline: 1.2862x; 1.2862x over previous
#include <cuda_runtime.h>
#include <cstdint>

// out[b,o] = sum_i w_out[o,i] * sin(x[b,i]*w_sin[o,i] + b_sin[o,i]) + b_out[o]
// B=2048, I=256, O=512.
// v7: R10 pipeline (cp.async double-buffered, 1 barrier pair/chunk) with the
// deg-15 Taylor poly replaced by a deg-9 Chebyshev poly on [-3,3] (err<7e-6;
// tolerance is 1e-3). Saves ~8 issue slots per warp-i-step (issue-bound kernel).

#define B_DIM 2048
#define I_DIM 256
#define O_DIM 512

#define BM 32   // b-tile per block
#define BO 32   // o-tile per block
#define KC 32   // i-chunk
#define XSP 36  // xs row pitch (floats), 16B-aligned rows

// degree-9 odd Chebyshev-fit sin on [-3,3]; max abs err ~4e-6 (args here <2.8).
// sin(u) ~ u*(a1 + a3 u^2 + a5 u^4 + a7 u^6 + a9 u^8); literal coeffs -> FFMA-imm.
__device__ __forceinline__ float poly_sin(float u) {
    float s = u * u;
    float p =  2.1956400e-06f;                 // a9
    p = fmaf(p, s, -1.9353920e-04f);           // a7
    p = fmaf(p, s,  8.3144200e-03f);           // a5
    p = fmaf(p, s, -1.6663634e-01f);           // a3
    p = fmaf(p, s,  9.9998620e-01f);           // a1
    return u * p;
}

__device__ __forceinline__ uint32_t smem_addr(const void* p) {
    uint32_t a;
    asm("{ .reg .u64 t; cvta.to.shared.u64 t, %1; cvt.u32.u64 %0, t; }" : "=r"(a) : "l"(p));
    return a;
}
__device__ __forceinline__ void cpa4(uint32_t dst, const void* src) {
    asm volatile("cp.async.ca.shared.global [%0], [%1], 4;" :: "r"(dst), "l"(src));
}
__device__ __forceinline__ void cpa8(uint32_t dst, const void* src) {
    asm volatile("cp.async.ca.shared.global [%0], [%1], 8;" :: "r"(dst), "l"(src));
}

struct SmemBuf {
    float  xs[KC][XSP];        // transposed x: xs[i][b]     4608 B
    float2 ws[BO][KC + 1];     // (w_out, w_sin)             8448 B (row pitch 264B)
    float  bs[BO][KC + 1];     // b_sin                      4224 B
};                              // 17280 B; x2 buffers = 34560 B

__global__ __launch_bounds__(128, 6)
void trigo_linear_kernel(const float* __restrict__ x,
                         const float* __restrict__ weight,
                         const float* __restrict__ bias,
                         float* __restrict__ out)
{
    __shared__ SmemBuf buf[2];

    const int tid     = threadIdx.x;       // 128 threads = 4 warps
    const int o_local = tid & 31;
    const int bg      = tid >> 5;          // warp -> b-group (8 b's)
    const int b_tile  = blockIdx.x * BM;
    const int o_tile  = blockIdx.y * BO;
    const int o       = o_tile + o_local;
    const int bg8     = bg * 8;

    const float2* __restrict__ wg = (const float2*)weight;  // [O][I] float2

    const int xi = tid & 31;               // i-index for x staging (coalesced)
    const int xq = tid >> 5;

    // ---- stage one chunk (i-range [cc, cc+KC)) into buf[sb] via cp.async ----
    auto stage = [&](int sb, int cc) {
        SmemBuf* S = &buf[sb];
        // x transposed: 8 x 4B per thread (lanes coalesced over xi)
        {
            const int b0 = xq * 8;
            #pragma unroll
            for (int k = 0; k < 8; k++)
                cpa4(smem_addr(&S->xs[xi][b0 + k]),
                     &x[(size_t)(b_tile + b0 + k) * I_DIM + cc + xi]);
        }
        // ws: 8B per op (one float2); 1024 ops / 128 thr = 8 each. 8B-aligned dst.
        #pragma unroll
        for (int j = 0; j < 8; j++) {
            int t  = tid + j * 128;
            int ol = t >> 5;
            int il = t & 31;
            cpa8(smem_addr(&S->ws[ol][il]),
                 &wg[(size_t)(o_tile + ol) * I_DIM + cc + il]);
        }
        // bs: 4B each (bias row pitch 257 floats -> no wide alignment)
        #pragma unroll
        for (int j = 0; j < 8; j++) {
            int t  = tid + j * 128;
            int ol = t >> 5;
            int il = t & 31;
            cpa4(smem_addr(&S->bs[ol][il]),
                 &bias[(size_t)(o_tile + ol) * (I_DIM + 1) + cc + il]);
        }
        asm volatile("cp.async.commit_group;" ::: "memory");
    };

    float acc[8];
    #pragma unroll
    for (int k = 0; k < 8; k++) acc[k] = 0.0f;

    // prologue: prefetch chunk 0
    stage(0, 0);

    const int NCHUNK = I_DIM / KC;         // 8
    for (int c = 0; c < NCHUNK; c++) {
        // chunk c's copies were committed one full compute-chunk ago
        asm volatile("cp.async.wait_group 0;" ::: "memory");
        __syncthreads();   // data visible to all warps; everyone past compute c-1

        // prefetch chunk c+1 into the other buffer (safe: buffer freed by barrier)
        if (c + 1 < NCHUNK) stage((c + 1) & 1, (c + 1) * KC);

        const SmemBuf* S = &buf[c & 1];
        #pragma unroll 4
        for (int i = 0; i < KC; i++) {
            float2 w   = S->ws[o_local][i];   // w.x = w_out, w.y = w_sin
            float  bsv = S->bs[o_local][i];
            float4 xa  = *(const float4*)&S->xs[i][bg8];      // broadcast LDS.128
            float4 xb  = *(const float4*)&S->xs[i][bg8 + 4];

            acc[0] = fmaf(w.x, poly_sin(fmaf(xa.x, w.y, bsv)), acc[0]);
            acc[1] = fmaf(w.x, poly_sin(fmaf(xa.y, w.y, bsv)), acc[1]);
            acc[2] = fmaf(w.x, __sinf(fmaf(xa.z, w.y, bsv)), acc[2]);
            acc[3] = fmaf(w.x, __sinf(fmaf(xa.w, w.y, bsv)), acc[3]);
            acc[4] = fmaf(w.x, __sinf(fmaf(xb.x, w.y, bsv)), acc[4]);
            acc[5] = fmaf(w.x, __sinf(fmaf(xb.y, w.y, bsv)), acc[5]);
            acc[6] = fmaf(w.x, __sinf(fmaf(xb.z, w.y, bsv)), acc[6]);
            acc[7] = fmaf(w.x, __sinf(fmaf(xb.w, w.y, bsv)), acc[7]);
        }
        __syncthreads();   // all warps done reading buf[c&1] before it's re-staged
    }

    const float b_out = bias[(size_t)o * (I_DIM + 1) + I_DIM];

    // warp lanes write consecutive o -> coalesced 128B rows
    #pragma unroll
    for (int k = 0; k < 8; k++) {
        out[(size_t)(b_tile + bg8 + k) * O_DIM + o] = acc[k] + b_out;
    }
}

extern "C" void kernel_launch(void* const* d_in, const int* in_sizes, int n_in,
                              void* d_out, int out_size)
{
    const float* x      = (const float*)d_in[0];
    const float* weight = (const float*)d_in[1];
    const float* bias   = (const float*)d_in[2];
    float* out          = (float*)d_out;

    dim3 grid(B_DIM / BM, O_DIM / BO);   // 64 x 16 = 1024 blocks, 128 thr each
    trigo_linear_kernel<<<grid, 128>>>(x, weight, bias, out);
}

// round 14
// speedup vs baseline: 1.3234x; 1.0289x over previous
#include <cuda_runtime.h>
#include <cstdint>

// out[b,o] = sum_i w_out[o,i] * sin(x[b,i]*w_sin[o,i] + b_sin[o,i]) + b_out[o]
// B=2048, I=256, O=512.
// v8: R13 inner loop (deg-9 poly x2 + 6 MUFU sins), occupancy push:
// KC=16 halves smem (17.7 KB double-buffered), __launch_bounds__(128,8)
// caps regs at 64 -> 8 blocks/SM (32 warps, was 24).

#define B_DIM 2048
#define I_DIM 256
#define O_DIM 512

#define BM 32   // b-tile per block
#define BO 32   // o-tile per block
#define KC 16   // i-chunk
#define XSP 36  // xs row pitch (floats), 16B-aligned rows

// degree-9 odd Chebyshev-fit sin on [-3,3]; max abs err ~4e-6 (args here <2.8).
__device__ __forceinline__ float poly_sin(float u) {
    float s = u * u;
    float p =  2.1956400e-06f;                 // a9
    p = fmaf(p, s, -1.9353920e-04f);           // a7
    p = fmaf(p, s,  8.3144200e-03f);           // a5
    p = fmaf(p, s, -1.6663634e-01f);           // a3
    p = fmaf(p, s,  9.9998620e-01f);           // a1
    return u * p;
}

__device__ __forceinline__ uint32_t smem_addr(const void* p) {
    uint32_t a;
    asm("{ .reg .u64 t; cvta.to.shared.u64 t, %1; cvt.u32.u64 %0, t; }" : "=r"(a) : "l"(p));
    return a;
}
__device__ __forceinline__ void cpa4(uint32_t dst, const void* src) {
    asm volatile("cp.async.ca.shared.global [%0], [%1], 4;" :: "r"(dst), "l"(src));
}
__device__ __forceinline__ void cpa8(uint32_t dst, const void* src) {
    asm volatile("cp.async.ca.shared.global [%0], [%1], 8;" :: "r"(dst), "l"(src));
}

struct SmemBuf {
    float  xs[KC][XSP];        // transposed x: xs[i][b]     2304 B
    float2 ws[BO][KC + 1];     // (w_out, w_sin)             4352 B (pitch 136B, 8B-aligned)
    float  bs[BO][KC + 1];     // b_sin                      2176 B
};                              // 8832 B; x2 buffers = 17664 B

__global__ __launch_bounds__(128, 8)
void trigo_linear_kernel(const float* __restrict__ x,
                         const float* __restrict__ weight,
                         const float* __restrict__ bias,
                         float* __restrict__ out)
{
    __shared__ SmemBuf buf[2];

    const int tid     = threadIdx.x;       // 128 threads = 4 warps
    const int o_local = tid & 31;
    const int bg      = tid >> 5;          // warp -> b-group (8 b's)
    const int b_tile  = blockIdx.x * BM;
    const int o_tile  = blockIdx.y * BO;
    const int o       = o_tile + o_local;
    const int bg8     = bg * 8;

    const float2* __restrict__ wg = (const float2*)weight;  // [O][I] float2

    const int xi = tid & 15;               // i-index for x staging (coalesced)
    const int xq = tid >> 4;               // 0..7 -> b-quad

    // ---- stage one chunk (i-range [cc, cc+KC)) into buf[sb] via cp.async ----
    auto stage = [&](int sb, int cc) {
        SmemBuf* S = &buf[sb];
        // x transposed: 4 x 4B per thread (lanes coalesced over xi)
        {
            const int b0 = xq * 4;
            #pragma unroll
            for (int k = 0; k < 4; k++)
                cpa4(smem_addr(&S->xs[xi][b0 + k]),
                     &x[(size_t)(b_tile + b0 + k) * I_DIM + cc + xi]);
        }
        // ws: 8B per op; 512 float2 / 128 thr = 4 each. dst 8B-aligned (pitch 136B).
        #pragma unroll
        for (int j = 0; j < 4; j++) {
            int t  = tid + j * 128;
            int ol = t >> 4;
            int il = t & 15;
            cpa8(smem_addr(&S->ws[ol][il]),
                 &wg[(size_t)(o_tile + ol) * I_DIM + cc + il]);
        }
        // bs: 4B each
        #pragma unroll
        for (int j = 0; j < 4; j++) {
            int t  = tid + j * 128;
            int ol = t >> 4;
            int il = t & 15;
            cpa4(smem_addr(&S->bs[ol][il]),
                 &bias[(size_t)(o_tile + ol) * (I_DIM + 1) + cc + il]);
        }
        asm volatile("cp.async.commit_group;" ::: "memory");
    };

    float acc[8];
    #pragma unroll
    for (int k = 0; k < 8; k++) acc[k] = 0.0f;

    // prologue: prefetch chunk 0
    stage(0, 0);

    const int NCHUNK = I_DIM / KC;         // 16
    for (int c = 0; c < NCHUNK; c++) {
        asm volatile("cp.async.wait_group 0;" ::: "memory");
        __syncthreads();   // data visible; everyone past compute c-1

        if (c + 1 < NCHUNK) stage((c + 1) & 1, (c + 1) * KC);

        const SmemBuf* S = &buf[c & 1];
        #pragma unroll
        for (int i = 0; i < KC; i++) {
            float2 w   = S->ws[o_local][i];   // w.x = w_out, w.y = w_sin
            float  bsv = S->bs[o_local][i];
            float4 xa  = *(const float4*)&S->xs[i][bg8];      // broadcast LDS.128
            float4 xb  = *(const float4*)&S->xs[i][bg8 + 4];

            acc[0] = fmaf(w.x, poly_sin(fmaf(xa.x, w.y, bsv)), acc[0]);
            acc[1] = fmaf(w.x, poly_sin(fmaf(xa.y, w.y, bsv)), acc[1]);
            acc[2] = fmaf(w.x, __sinf(fmaf(xa.z, w.y, bsv)), acc[2]);
            acc[3] = fmaf(w.x, __sinf(fmaf(xa.w, w.y, bsv)), acc[3]);
            acc[4] = fmaf(w.x, __sinf(fmaf(xb.x, w.y, bsv)), acc[4]);
            acc[5] = fmaf(w.x, __sinf(fmaf(xb.y, w.y, bsv)), acc[5]);
            acc[6] = fmaf(w.x, __sinf(fmaf(xb.z, w.y, bsv)), acc[6]);
            acc[7] = fmaf(w.x, __sinf(fmaf(xb.w, w.y, bsv)), acc[7]);
        }
        __syncthreads();   // all warps done reading buf[c&1] before re-staging
    }

    const float b_out = bias[(size_t)o * (I_DIM + 1) + I_DIM];

    // warp lanes write consecutive o -> coalesced 128B rows
    #pragma unroll
    for (int k = 0; k < 8; k++) {
        out[(size_t)(b_tile + bg8 + k) * O_DIM + o] = acc[k] + b_out;
    }
}

extern "C" void kernel_launch(void* const* d_in, const int* in_sizes, int n_in,
                              void* d_out, int out_size)
{
    const float* x      = (const float*)d_in[0];
    const float* weight = (const float*)d_in[1];
    const float* bias   = (const float*)d_in[2];
    float* out          = (float*)d_out;

    dim3 grid(B_DIM / BM, O_DIM / BO);   // 64 x 16 = 1024 blocks, 128 thr each
    trigo_linear_kernel<<<grid, 128>>>(x, weight, bias, out);
}